// round 10
// baseline (speedup 1.0000x reference)
#include <cuda_runtime.h>

// NetNew_17162689315115 — R10: 2 rows/thread over R9's all-constant layout.
// Every LDC.128 weight load is shared by both rows (8 FMAs per load), halving
// constant-port traffic; scalar FFMA (full-rate) does the math. Exact rows
// (peel/tail), fully unrolled, h register-resident. Numerics == R1.

struct NetParams {
    const float* x;
    float*       out;
    int          B;
};
struct PrepParams {
    const float* W[9];   // W1..W8, Wf
};

template <int L> struct LC {
    static constexpr int DIN  = 8 + 9 * L;
    static constexpr int BASE = 72 - 9 * L;   // first input feature index
};
template <int L> struct WOff;
template <> struct WOff<0> { static constexpr int V = 0; };
template <int L> struct WOff {
    static constexpr int V = WOff<L - 1>::V + 13 * LC<L - 1>::DIN;
};
static constexpr int WF_OFF   = WOff<7>::V + 13 * LC<7>::DIN;  // 4108
static constexpr int CW_TOTAL = WF_OFF + 80;                   // 4188

__constant__ __align__(16) float cw[CW_TOTAL];
__device__   __align__(16) float g_wpad[CW_TOTAL];

__device__ __forceinline__ float clip_mag(float v, float mx) {
    // matches jnp.where(|v| >= mx, v * |mx/v|, v) incl. inf -> NaN edge case
    if (fabsf(v) >= mx) v = v * fabsf(mx / v);
    return v;
}

// ---- prep: concatenate W1..W8 (exact row-major) ++ Wf into scratch ----
__global__ void netnew_prep(PrepParams pp) {
#define STAGE(L)                                                              \
    {                                                                         \
        constexpr int N = 13 * LC<L>::DIN;                                    \
        const float* g = pp.W[L];                                             \
        for (int i = threadIdx.x; i < N; i += blockDim.x)                     \
            g_wpad[WOff<L>::V + i] = g[i];                                    \
    }
    STAGE(0) STAGE(1) STAGE(2) STAGE(3) STAGE(4) STAGE(5) STAGE(6) STAGE(7)
#undef STAGE
    for (int i = threadIdx.x; i < 80; i += blockDim.x)
        g_wpad[WF_OFF + i] = pp.W[8][i];
}

// ---- elementwise epilogue (identical order to R1) ----
__device__ __forceinline__ void apply_ops(const float* __restrict__ z,
                                          float* __restrict__ o) {
    o[0] = z[0] + z[1];
    o[1] = z[2] - z[3];
    o[2] = clip_mag(z[4] * z[5], 99999999.0f);
    {
        float b   = z[7];
        float den = (b == 0.0f) ? (b + 0.0001f) : b;
        o[3] = clip_mag(z[6] / den, 9999.0f);
    }
    o[4] = sinf(z[8]);
    o[5] = cosf(z[9]);
    {
        float a = z[10];
        if (a >= 17.0f) a = a * (17.0f / a);
        o[6] = expf(a);
    }
    o[7] = logf(fabsf(z[11]));
    o[8] = clip_mag(z[12] * z[12], 99999999.0f);
}

template <int L>
__device__ __forceinline__ void do_layer2(float* __restrict__ ha,
                                          float* __restrict__ hb) {
    constexpr int DIN  = LC<L>::DIN;
    constexpr int BASE = LC<L>::BASE;

    float za[13], zb[13];
#pragma unroll
    for (int j = 0; j < 13; ++j) {
        const int roff = WOff<L>::V + j * DIN;   // compile-time after unroll
        float aa = 0.0f, ab = 0.0f;
        int k = 0;
        const int mis = roff & 3;                // compile-time per j
        if (mis != 0) {
            const int peel = 4 - mis;
#pragma unroll
            for (int t = 0; t < 3; ++t) {
                if (t < peel && k < DIN) {
                    const float w = cw[roff + k];
                    aa = fmaf(w, ha[BASE + k], aa);
                    ab = fmaf(w, hb[BASE + k], ab);
                    ++k;
                }
            }
        }
#pragma unroll
        for (; k + 3 < DIN; k += 4) {
            const float4 w = *reinterpret_cast<const float4*>(cw + roff + k);
            aa = fmaf(w.x, ha[BASE + k + 0], aa);
            ab = fmaf(w.x, hb[BASE + k + 0], ab);
            aa = fmaf(w.y, ha[BASE + k + 1], aa);
            ab = fmaf(w.y, hb[BASE + k + 1], ab);
            aa = fmaf(w.z, ha[BASE + k + 2], aa);
            ab = fmaf(w.z, hb[BASE + k + 2], ab);
            aa = fmaf(w.w, ha[BASE + k + 3], aa);
            ab = fmaf(w.w, hb[BASE + k + 3], ab);
        }
#pragma unroll
        for (; k < DIN; ++k) {
            const float w = cw[roff + k];
            aa = fmaf(w, ha[BASE + k], aa);
            ab = fmaf(w, hb[BASE + k], ab);
        }
        za[j] = aa;
        zb[j] = ab;
    }

    apply_ops(za, ha + (BASE - 9));
    apply_ops(zb, hb + (BASE - 9));
}

__global__ __launch_bounds__(128, 2)
void netnew_kernel10(NetParams p) {
    const int t  = blockIdx.x * blockDim.x + threadIdx.x;
    const int r0 = 2 * t;
    if (r0 >= p.B) return;

    // h layout per row: [outs8 | ... | outs1 | x]; x at [72..79].
    float ha[80], hb[80];
    {
        const float4* xr = reinterpret_cast<const float4*>(p.x + (size_t)r0 * 8);
        float4 a0 = xr[0], a1 = xr[1];   // row r0
        float4 b0 = xr[2], b1 = xr[3];   // row r0+1
        ha[72] = a0.x; ha[73] = a0.y; ha[74] = a0.z; ha[75] = a0.w;
        ha[76] = a1.x; ha[77] = a1.y; ha[78] = a1.z; ha[79] = a1.w;
        hb[72] = b0.x; hb[73] = b0.y; hb[74] = b0.z; hb[75] = b0.w;
        hb[76] = b1.x; hb[77] = b1.y; hb[78] = b1.z; hb[79] = b1.w;
    }

    do_layer2<0>(ha, hb);
    do_layer2<1>(ha, hb);
    do_layer2<2>(ha, hb);
    do_layer2<3>(ha, hb);
    do_layer2<4>(ha, hb);
    do_layer2<5>(ha, hb);
    do_layer2<6>(ha, hb);
    do_layer2<7>(ha, hb);

    // final: out = dot(Wf, h[0..79]) for both rows, sequential ascending k
    float aa = 0.0f, ab = 0.0f;
#pragma unroll
    for (int k = 0; k < 80; k += 4) {
        const float4 w = *reinterpret_cast<const float4*>(cw + WF_OFF + k);
        aa = fmaf(w.x, ha[k + 0], aa);
        ab = fmaf(w.x, hb[k + 0], ab);
        aa = fmaf(w.y, ha[k + 1], aa);
        ab = fmaf(w.y, hb[k + 1], ab);
        aa = fmaf(w.z, ha[k + 2], aa);
        ab = fmaf(w.z, hb[k + 2], ab);
        aa = fmaf(w.w, ha[k + 3], aa);
        ab = fmaf(w.w, hb[k + 3], ab);
    }
    p.out[r0]     = aa;
    p.out[r0 + 1] = ab;
}

extern "C" void kernel_launch(void* const* d_in, const int* in_sizes, int n_in,
                              void* d_out, int out_size) {
    PrepParams pp;
    for (int i = 0; i < 9; ++i) pp.W[i] = (const float*)d_in[1 + i];

    NetParams p;
    p.x   = (const float*)d_in[0];
    p.out = (float*)d_out;
    p.B   = in_sizes[0] / 8;

    // stage concatenated weights, then one D2D copy into the constant bank
    netnew_prep<<<1, 256>>>(pp);
    void* src = nullptr;
    cudaGetSymbolAddress(&src, g_wpad);
    cudaMemcpyToSymbolAsync(cw, src, CW_TOTAL * sizeof(float), 0,
                            cudaMemcpyDeviceToDevice, 0);

    const int threads = 128;
    const int pairs   = p.B / 2;
    const int blocks  = (pairs + threads - 1) / threads;
    netnew_kernel10<<<blocks, threads>>>(p);
}

// round 12
// speedup vs baseline: 1.2703x; 1.2703x over previous
#include <cuda_runtime.h>

// NetNew_17162689315115 — R12: R11 (dual-port uniform weight stream:
// L0-4+Wf from __constant__/LDC, L5-7 from global/__ldg LDG.128) with the
// alignment bug fixed: LDG region base padded to a 16B boundary
// (GW_BASE = round_up(CW_TOTAL,4)). Numerics == R1.

struct NetParams {
    const float* x;
    const float* wg;     // LDG-side weights (g_scratch + GW_BASE)
    float*       out;
    int          B;
};
struct PrepParams {
    const float* W[9];   // W1..W8, Wf
};

template <int L> struct LC {
    static constexpr int DIN  = 8 + 9 * L;
    static constexpr int BASE = 72 - 9 * L;   // first input feature index
};

// constant side: L0..L4 exact rows, then Wf
template <int L> struct COff;
template <> struct COff<0> { static constexpr int V = 0; };
template <int L> struct COff {
    static constexpr int V = COff<L - 1>::V + 13 * LC<L - 1>::DIN;
};
static constexpr int WF_OFF   = COff<4>::V + 13 * LC<4>::DIN;  // 1690
static constexpr int CW_TOTAL = WF_OFF + 80;                   // 1770

// LDG side: L5,L6,L7 exact rows, region base 16B-aligned
static constexpr int GW_BASE = (CW_TOTAL + 3) & ~3;            // 1772
template <int L> struct GOff;
template <> struct GOff<5> { static constexpr int V = 0; };
template <> struct GOff<6> { static constexpr int V = 13 * LC<5>::DIN; };               // 689
template <> struct GOff<7> { static constexpr int V = 13 * (LC<5>::DIN + LC<6>::DIN); };// 1495
static constexpr int GW_TOTAL = 13 * (LC<5>::DIN + LC<6>::DIN + LC<7>::DIN);            // 2418

__constant__ __align__(16) float cw[CW_TOTAL];
__device__   __align__(16) float g_scratch[GW_BASE + GW_TOTAL];

__device__ __forceinline__ float clip_mag(float v, float mx) {
    // matches jnp.where(|v| >= mx, v * |mx/v|, v) incl. inf -> NaN edge case
    if (fabsf(v) >= mx) v = v * fabsf(mx / v);
    return v;
}

// ---- prep: pack [L0..L4, Wf | (pad) | L5, L6, L7] into scratch ----
__global__ void netnew_prep(PrepParams pp) {
#define STAGE_C(L)                                                            \
    {                                                                         \
        constexpr int N = 13 * LC<L>::DIN;                                    \
        const float* g = pp.W[L];                                             \
        for (int i = threadIdx.x; i < N; i += blockDim.x)                     \
            g_scratch[COff<L>::V + i] = g[i];                                 \
    }
    STAGE_C(0) STAGE_C(1) STAGE_C(2) STAGE_C(3) STAGE_C(4)
#undef STAGE_C
    for (int i = threadIdx.x; i < 80; i += blockDim.x)
        g_scratch[WF_OFF + i] = pp.W[8][i];
#define STAGE_G(L)                                                            \
    {                                                                         \
        constexpr int N = 13 * LC<L>::DIN;                                    \
        const float* g = pp.W[L];                                             \
        for (int i = threadIdx.x; i < N; i += blockDim.x)                     \
            g_scratch[GW_BASE + GOff<L>::V + i] = g[i];                       \
    }
    STAGE_G(5) STAGE_G(6) STAGE_G(7)
#undef STAGE_G
}

// ---- elementwise epilogue (identical order to R1) ----
__device__ __forceinline__ void apply_ops(const float* __restrict__ z,
                                          float* __restrict__ o) {
    o[0] = z[0] + z[1];
    o[1] = z[2] - z[3];
    o[2] = clip_mag(z[4] * z[5], 99999999.0f);
    {
        float b   = z[7];
        float den = (b == 0.0f) ? (b + 0.0001f) : b;
        o[3] = clip_mag(z[6] / den, 9999.0f);
    }
    o[4] = sinf(z[8]);
    o[5] = cosf(z[9]);
    {
        float a = z[10];
        if (a >= 17.0f) a = a * (17.0f / a);
        o[6] = expf(a);
    }
    o[7] = logf(fabsf(z[11]));
    o[8] = clip_mag(z[12] * z[12], 99999999.0f);
}

// ---- constant-sourced layer (L = 0..4) ----
template <int L>
__device__ __forceinline__ void do_layer_c(float* __restrict__ h) {
    constexpr int DIN  = LC<L>::DIN;
    constexpr int BASE = LC<L>::BASE;

    float z[13];
#pragma unroll
    for (int j = 0; j < 13; ++j) {
        const int roff = COff<L>::V + j * DIN;   // compile-time after unroll
        float acc = 0.0f;
        int k = 0;
        const int mis = roff & 3;
        if (mis != 0) {
            const int peel = 4 - mis;
#pragma unroll
            for (int t = 0; t < 3; ++t) {
                if (t < peel && k < DIN) {
                    acc = fmaf(cw[roff + k], h[BASE + k], acc);
                    ++k;
                }
            }
        }
#pragma unroll
        for (; k + 3 < DIN; k += 4) {
            const float4 w = *reinterpret_cast<const float4*>(cw + roff + k);
            acc = fmaf(w.x, h[BASE + k + 0], acc);
            acc = fmaf(w.y, h[BASE + k + 1], acc);
            acc = fmaf(w.z, h[BASE + k + 2], acc);
            acc = fmaf(w.w, h[BASE + k + 3], acc);
        }
#pragma unroll
        for (; k < DIN; ++k)
            acc = fmaf(cw[roff + k], h[BASE + k], acc);
        z[j] = acc;
    }
    apply_ops(z, h + (BASE - 9));
}

// ---- global(LDG)-sourced layer (L = 5..7) ----
template <int L>
__device__ __forceinline__ void do_layer_g(float* __restrict__ h,
                                           const float* __restrict__ wg) {
    constexpr int DIN  = LC<L>::DIN;
    constexpr int BASE = LC<L>::BASE;

    float z[13];
#pragma unroll
    for (int j = 0; j < 13; ++j) {
        const int roff = GOff<L>::V + j * DIN;   // compile-time after unroll
        float acc = 0.0f;
        int k = 0;
        const int mis = roff & 3;
        if (mis != 0) {
            const int peel = 4 - mis;
#pragma unroll
            for (int t = 0; t < 3; ++t) {
                if (t < peel && k < DIN) {
                    acc = fmaf(__ldg(wg + roff + k), h[BASE + k], acc);
                    ++k;
                }
            }
        }
#pragma unroll
        for (; k + 3 < DIN; k += 4) {
            const float4 w = __ldg(reinterpret_cast<const float4*>(wg + roff + k));
            acc = fmaf(w.x, h[BASE + k + 0], acc);
            acc = fmaf(w.y, h[BASE + k + 1], acc);
            acc = fmaf(w.z, h[BASE + k + 2], acc);
            acc = fmaf(w.w, h[BASE + k + 3], acc);
        }
#pragma unroll
        for (; k < DIN; ++k)
            acc = fmaf(__ldg(wg + roff + k), h[BASE + k], acc);
        z[j] = acc;
    }
    apply_ops(z, h + (BASE - 9));
}

__global__ __launch_bounds__(128, 6)
void netnew_kernel12(NetParams p) {
    const int row = blockIdx.x * blockDim.x + threadIdx.x;
    if (row >= p.B) return;

    const float* wg = p.wg;

    // h layout: [outs8 | outs7 | ... | outs1 | x]; x at [72..79].
    float h[80];
    {
        const float4* xr = reinterpret_cast<const float4*>(p.x + (size_t)row * 8);
        float4 a = xr[0], b = xr[1];
        h[72] = a.x; h[73] = a.y; h[74] = a.z; h[75] = a.w;
        h[76] = b.x; h[77] = b.y; h[78] = b.z; h[79] = b.w;
    }

    do_layer_c<0>(h);
    do_layer_c<1>(h);
    do_layer_c<2>(h);
    do_layer_c<3>(h);
    do_layer_c<4>(h);
    do_layer_g<5>(h, wg);
    do_layer_g<6>(h, wg);
    do_layer_g<7>(h, wg);

    // final: out = dot(Wf, h[0..79]) from constant, sequential ascending k
    float acc = 0.0f;
#pragma unroll
    for (int k = 0; k < 80; k += 4) {
        const float4 w = *reinterpret_cast<const float4*>(cw + WF_OFF + k);
        acc = fmaf(w.x, h[k + 0], acc);
        acc = fmaf(w.y, h[k + 1], acc);
        acc = fmaf(w.z, h[k + 2], acc);
        acc = fmaf(w.w, h[k + 3], acc);
    }
    p.out[row] = acc;
}

extern "C" void kernel_launch(void* const* d_in, const int* in_sizes, int n_in,
                              void* d_out, int out_size) {
    PrepParams pp;
    for (int i = 0; i < 9; ++i) pp.W[i] = (const float*)d_in[1 + i];

    // pack both regions into scratch, then one D2D copy of the prefix into cw
    netnew_prep<<<1, 256>>>(pp);
    void* scratch = nullptr;
    cudaGetSymbolAddress(&scratch, g_scratch);
    cudaMemcpyToSymbolAsync(cw, scratch, CW_TOTAL * sizeof(float), 0,
                            cudaMemcpyDeviceToDevice, 0);

    NetParams p;
    p.x   = (const float*)d_in[0];
    p.wg  = (const float*)scratch + GW_BASE;
    p.out = (float*)d_out;
    p.B   = in_sizes[0] / 8;

    const int threads = 128;
    const int blocks  = (p.B + threads - 1) / threads;
    netnew_kernel12<<<blocks, threads>>>(p);
}

// round 13
// speedup vs baseline: 1.9248x; 1.5152x over previous
#include <cuda_runtime.h>

// NetNew_17162689315115 — R13: consolidation.
// Kernel = R9 (all weights in __constant__, exact concatenated rows, LDC.128
// + peel/tail, h[80] register-resident, fully unrolled)
// Staging = R7 (prep kernel + single D2D memcpyToSymbol: ~6us less graph
// overhead than 9 separate copies)
// Occupancy = launch_bounds(128,7): 28 warps/SM (reg cap 73).
// Numerics identical to R1 (sequential ascending-k accumulation).

struct NetParams {
    const float* x;
    float*       out;
    int          B;
};
struct PrepParams {
    const float* W[9];   // W1..W8, Wf
};

template <int L> struct LC {
    static constexpr int DIN  = 8 + 9 * L;
    static constexpr int BASE = 72 - 9 * L;   // first input feature index
};
template <int L> struct WOff;
template <> struct WOff<0> { static constexpr int V = 0; };
template <int L> struct WOff {
    static constexpr int V = WOff<L - 1>::V + 13 * LC<L - 1>::DIN;
};
static constexpr int WF_OFF   = WOff<7>::V + 13 * LC<7>::DIN;  // 4108
static constexpr int CW_TOTAL = WF_OFF + 80;                   // 4188

__constant__ __align__(16) float cw[CW_TOTAL];
__device__   __align__(16) float g_wpad[CW_TOTAL];

__device__ __forceinline__ float clip_mag(float v, float mx) {
    // matches jnp.where(|v| >= mx, v * |mx/v|, v) incl. inf -> NaN edge case
    if (fabsf(v) >= mx) v = v * fabsf(mx / v);
    return v;
}

// ---- prep: concatenate W1..W8 (exact row-major) ++ Wf into scratch ----
__global__ void netnew_prep(PrepParams pp) {
#define STAGE(L)                                                              \
    {                                                                         \
        constexpr int N = 13 * LC<L>::DIN;                                    \
        const float* g = pp.W[L];                                             \
        for (int i = threadIdx.x; i < N; i += blockDim.x)                     \
            g_wpad[WOff<L>::V + i] = g[i];                                    \
    }
    STAGE(0) STAGE(1) STAGE(2) STAGE(3) STAGE(4) STAGE(5) STAGE(6) STAGE(7)
#undef STAGE
    for (int i = threadIdx.x; i < 80; i += blockDim.x)
        g_wpad[WF_OFF + i] = pp.W[8][i];
}

template <int L>
__device__ __forceinline__ void do_layer(float* __restrict__ h) {
    constexpr int DIN  = LC<L>::DIN;
    constexpr int BASE = LC<L>::BASE;

    float z[13];
#pragma unroll
    for (int j = 0; j < 13; ++j) {
        const int roff = WOff<L>::V + j * DIN;   // compile-time after unroll
        float acc = 0.0f;
        int k = 0;
        const int mis = roff & 3;                // compile-time per j
        if (mis != 0) {
            const int peel = 4 - mis;
#pragma unroll
            for (int t = 0; t < 3; ++t) {
                if (t < peel && k < DIN) {
                    acc = fmaf(cw[roff + k], h[BASE + k], acc);
                    ++k;
                }
            }
        }
#pragma unroll
        for (; k + 3 < DIN; k += 4) {
            const float4 w = *reinterpret_cast<const float4*>(cw + roff + k);
            acc = fmaf(w.x, h[BASE + k + 0], acc);
            acc = fmaf(w.y, h[BASE + k + 1], acc);
            acc = fmaf(w.z, h[BASE + k + 2], acc);
            acc = fmaf(w.w, h[BASE + k + 3], acc);
        }
#pragma unroll
        for (; k < DIN; ++k)
            acc = fmaf(cw[roff + k], h[BASE + k], acc);
        z[j] = acc;
    }

    float* o = h + (BASE - 9);
    o[0] = z[0] + z[1];
    o[1] = z[2] - z[3];
    o[2] = clip_mag(z[4] * z[5], 99999999.0f);
    {
        float b   = z[7];
        float den = (b == 0.0f) ? (b + 0.0001f) : b;
        o[3] = clip_mag(z[6] / den, 9999.0f);
    }
    o[4] = sinf(z[8]);
    o[5] = cosf(z[9]);
    {
        float a = z[10];
        if (a >= 17.0f) a = a * (17.0f / a);
        o[6] = expf(a);
    }
    o[7] = logf(fabsf(z[11]));
    o[8] = clip_mag(z[12] * z[12], 99999999.0f);
}

__global__ __launch_bounds__(128, 7)
void netnew_kernel13(NetParams p) {
    const int row = blockIdx.x * blockDim.x + threadIdx.x;
    if (row >= p.B) return;

    // h layout: [outs8 | outs7 | ... | outs1 | x]; x at [72..79].
    float h[80];
    {
        const float4* xr = reinterpret_cast<const float4*>(p.x + (size_t)row * 8);
        float4 a = xr[0], b = xr[1];
        h[72] = a.x; h[73] = a.y; h[74] = a.z; h[75] = a.w;
        h[76] = b.x; h[77] = b.y; h[78] = b.z; h[79] = b.w;
    }

    do_layer<0>(h);
    do_layer<1>(h);
    do_layer<2>(h);
    do_layer<3>(h);
    do_layer<4>(h);
    do_layer<5>(h);
    do_layer<6>(h);
    do_layer<7>(h);

    // final: out = dot(Wf, h[0..79]), sequential ascending k (WF_OFF%4==0)
    float acc = 0.0f;
#pragma unroll
    for (int k = 0; k < 80; k += 4) {
        const float4 w = *reinterpret_cast<const float4*>(cw + WF_OFF + k);
        acc = fmaf(w.x, h[k + 0], acc);
        acc = fmaf(w.y, h[k + 1], acc);
        acc = fmaf(w.z, h[k + 2], acc);
        acc = fmaf(w.w, h[k + 3], acc);
    }
    p.out[row] = acc;
}

extern "C" void kernel_launch(void* const* d_in, const int* in_sizes, int n_in,
                              void* d_out, int out_size) {
    PrepParams pp;
    for (int i = 0; i < 9; ++i) pp.W[i] = (const float*)d_in[1 + i];

    NetParams p;
    p.x   = (const float*)d_in[0];
    p.out = (float*)d_out;
    p.B   = in_sizes[0] / 8;

    // stage concatenated weights, then ONE D2D copy into the constant bank
    netnew_prep<<<1, 256>>>(pp);
    void* src = nullptr;
    cudaGetSymbolAddress(&src, g_wpad);
    cudaMemcpyToSymbolAsync(cw, src, CW_TOTAL * sizeof(float), 0,
                            cudaMemcpyDeviceToDevice, 0);

    const int threads = 128;
    const int blocks  = (p.B + threads - 1) / threads;
    netnew_kernel13<<<blocks, threads>>>(p);
}